// round 2
// baseline (speedup 1.0000x reference)
#include <cuda_runtime.h>
#include <cuda_bf16.h>
#include <cstdint>

// Problem constants (fixed by the dataset)
#define B 2
#define N 16384
#define M 4096
#define E 32
#define C 64
#define S 32
#define NCH 96            // E + C
#define R2 0.01f          // float32(0.1*0.1) as JAX casts the weak scalar

// ---------------- scratch (device globals: no runtime allocation) -----------
__device__ float4 g_xyz4[B * N];            // packed xyz + precomputed ||p||^2
__device__ float  g_feat_t[(size_t)B * N * C];  // features transposed to (B,N,C)
__device__ int    g_idx[B * M * S];         // ball-query result indices

// XLA-style norm: multiply (rounded) then sequential reduce — NO fma.
__device__ __forceinline__ float norm3_nofma(float x, float y, float z) {
    return __fadd_rn(__fadd_rn(__fmul_rn(x, x), __fmul_rn(y, y)),
                     __fmul_rn(z, z));
}

// dot_general K=3: sequential fma accumulation (acc = fma(ak,bk,acc), acc0=0).
// fma(a0,b0,0) rounds identically to mul, so start with __fmul_rn.
__device__ __forceinline__ float dot3_fma(float ax, float ay, float az,
                                          float bx, float by, float bz) {
    return __fmaf_rn(az, bz, __fmaf_rn(ay, by, __fmul_rn(ax, bx)));
}

// ---------------- kernel 1: pack xyz -> float4 {x,y,z,||p||^2} --------------
__global__ void pack_xyz_kernel(const float* __restrict__ xyz) {
    int i = blockIdx.x * blockDim.x + threadIdx.x;
    if (i < B * N) {
        float x = xyz[3 * i + 0];
        float y = xyz[3 * i + 1];
        float z = xyz[3 * i + 2];
        g_xyz4[i] = make_float4(x, y, z, norm3_nofma(x, y, z));
    }
}

// ---------------- kernel 2: transpose features (B,C,N) -> (B,N,C) -----------
__global__ void transpose_feat_kernel(const float* __restrict__ f) {
    __shared__ float t[32][33];
    int b  = blockIdx.z;
    int n0 = blockIdx.x * 32;
    int c0 = blockIdx.y * 32;
#pragma unroll
    for (int i = 0; i < 32; i += 8) {
        t[threadIdx.y + i][threadIdx.x] =
            f[((size_t)(b * C + c0 + threadIdx.y + i)) * N + n0 + threadIdx.x];
    }
    __syncthreads();
#pragma unroll
    for (int i = 0; i < 32; i += 8) {
        g_feat_t[((size_t)b * N + n0 + threadIdx.y + i) * C + c0 + threadIdx.x] =
            t[threadIdx.x][threadIdx.y + i];
    }
}

// ---------------- kernel 3: ball query (warp per center) --------------------
// Ballot bit order == ascending original index order, matching the reference's
// top_k(-cand) semantics. Pads with first found index (or 0 if none).
__global__ __launch_bounds__(256) void ball_query_kernel(
        const float* __restrict__ new_xyz) {
    int warp = (blockIdx.x * blockDim.x + threadIdx.x) >> 5;
    int lane = threadIdx.x & 31;
    if (warp >= B * M) return;

    int b = warp >> 12;            // / M
    const float nx = new_xyz[3 * warp + 0];
    const float ny = new_xyz[3 * warp + 1];
    const float nz = new_xyz[3 * warp + 2];
    const float sn = norm3_nofma(nx, ny, nz);

    const float4* __restrict__ P = g_xyz4 + b * N;
    int* __restrict__ ob = g_idx + warp * S;

    const unsigned FULL = 0xFFFFFFFFu;
    const unsigned lt   = (1u << lane) - 1u;
    int cnt = 0;
    int first = 0;

    for (int j0 = 0; j0 < N && cnt < S; j0 += 128) {
        float4 p0 = P[j0 + lane];
        float4 p1 = P[j0 + 32 + lane];
        float4 p2 = P[j0 + 64 + lane];
        float4 p3 = P[j0 + 96 + lane];
#pragma unroll
        for (int u = 0; u < 4; u++) {
            float4 p = (u == 0) ? p0 : (u == 1) ? p1 : (u == 2) ? p2 : p3;
            int j = j0 + u * 32 + lane;
            // d2 = fl( fl(sn + sp) - 2*dot ); 2*dot is exact, single rounding
            float dot = dot3_fma(nx, ny, nz, p.x, p.y, p.z);
            float d2  = __fmaf_rn(-2.0f, dot, __fadd_rn(sn, p.w));
            bool hit  = d2 < R2;
            unsigned mask = __ballot_sync(FULL, hit);
            if (mask) {
                int pos = cnt + __popc(mask & lt);
                if (hit && pos < S) ob[pos] = j;
                if (cnt == 0) first = __shfl_sync(FULL, j, __ffs(mask) - 1);
                cnt += __popc(mask);
            }
            if (cnt >= S) break;   // uniform across warp
        }
    }
    if (lane >= cnt) ob[lane] = first;   // first==0 when cnt==0
}

// ---------------- kernel 4: gather + concat (block per center) --------------
// Phase 1: coalesced row reads (point rows are 128B/256B contiguous) staged
// into SMEM with an s-major -> ch-major transpose; Phase 2: coalesced 128B
// writes of out[b][ch][m][0:32].
__global__ __launch_bounds__(256) void gather_kernel(
        const float* __restrict__ xyz_embed,
        const float* __restrict__ new_xyz_embed,
        float* __restrict__ out) {
    __shared__ float tile[NCH * 33];
    __shared__ int   sidx[S];
    __shared__ float ce[E];

    int center = blockIdx.x;           // b*M + m
    int b = center >> 12;
    int m = center & (M - 1);
    int tid = threadIdx.x;

    if (tid < S)  sidx[tid] = g_idx[center * S + tid];
    if (tid < E)  ce[tid]   = new_xyz_embed[center * E + tid];
    __syncthreads();

    // Phase 1: read 32 points x 96 channels, store transposed in SMEM
    for (int t = tid; t < S * NCH; t += blockDim.x) {
        int s  = t / NCH;
        int ch = t - s * NCH;
        int p  = sidx[s];
        float v;
        if (ch < E) {
            v = xyz_embed[((size_t)b * N + p) * E + ch] - ce[ch];
        } else {
            v = g_feat_t[((size_t)b * N + p) * C + (ch - E)];
        }
        tile[ch * 33 + s] = v;
    }
    __syncthreads();

    // Phase 2: coalesced channel-row writes
    for (int t = tid; t < S * NCH; t += blockDim.x) {
        int ch = t >> 5;
        int s  = t & 31;
        out[(((size_t)b * NCH + ch) * M + m) * S + s] = tile[ch * 33 + s];
    }
}

// ---------------- launch ----------------------------------------------------
extern "C" void kernel_launch(void* const* d_in, const int* in_sizes, int n_in,
                              void* d_out, int out_size) {
    const float* xyz           = (const float*)d_in[0];
    const float* xyz_embed     = (const float*)d_in[1];
    const float* new_xyz       = (const float*)d_in[2];
    const float* new_xyz_embed = (const float*)d_in[3];
    const float* features      = (const float*)d_in[4];
    float* out = (float*)d_out;

    pack_xyz_kernel<<<(B * N + 255) / 256, 256>>>(xyz);
    transpose_feat_kernel<<<dim3(N / 32, C / 32, B), dim3(32, 8)>>>(features);
    ball_query_kernel<<<(B * M * 32 + 255) / 256, 256>>>(new_xyz);
    gather_kernel<<<B * M, 256>>>(xyz_embed, new_xyz_embed, out);
}

// round 4
// speedup vs baseline: 1.3166x; 1.3166x over previous
#include <cuda_runtime.h>
#include <cuda_bf16.h>
#include <cstdint>

#define B 2
#define N 16384
#define M 4096
#define E 32
#define C 64
#define S 32
#define NCH 96
#define R2 0.01f
#define TP 37              // tile row pad (floats) — see bank analysis

// ---------------- scratch ----------------------------------------------------
__device__ float4 g_xyz4[B * N];
__device__ __align__(16) float g_feat_t[(size_t)B * N * C];  // (B,N,C)
__device__ int    g_idx[B * M * S];

// XLA norm: mul (rounded) + sequential adds — NO fma.
__device__ __forceinline__ float norm3_nofma(float x, float y, float z) {
    return __fadd_rn(__fadd_rn(__fmul_rn(x, x), __fmul_rn(y, y)),
                     __fmul_rn(z, z));
}
// dot_general K=3: sequential fma chain; fma(a,b,0) == mul.
__device__ __forceinline__ float dot3_fma(float ax, float ay, float az,
                                          float bx, float by, float bz) {
    return __fmaf_rn(az, bz, __fmaf_rn(ay, by, __fmul_rn(ax, bx)));
}

// ---------------- kernel 1: pack xyz -> float4 {x,y,z,||p||^2} ---------------
__global__ void pack_xyz_kernel(const float* __restrict__ xyz) {
    int i = blockIdx.x * blockDim.x + threadIdx.x;
    if (i < B * N) {
        float x = xyz[3 * i + 0];
        float y = xyz[3 * i + 1];
        float z = xyz[3 * i + 2];
        g_xyz4[i] = make_float4(x, y, z, norm3_nofma(x, y, z));
    }
}

// ---------------- kernel 2: transpose features (B,C,N) -> (B,N,C) ------------
__global__ void transpose_feat_kernel(const float* __restrict__ f) {
    __shared__ float t[32][33];
    int b  = blockIdx.z;
    int n0 = blockIdx.x * 32;
    int c0 = blockIdx.y * 32;
#pragma unroll
    for (int i = 0; i < 32; i += 8) {
        t[threadIdx.y + i][threadIdx.x] =
            f[((size_t)(b * C + c0 + threadIdx.y + i)) * N + n0 + threadIdx.x];
    }
    __syncthreads();
#pragma unroll
    for (int i = 0; i < 32; i += 8) {
        g_feat_t[((size_t)b * N + n0 + threadIdx.y + i) * C + c0 + threadIdx.x] =
            t[threadIdx.x][threadIdx.y + i];
    }
}

// ---------------- kernel 3: ball query (warp per center) ---------------------
__global__ __launch_bounds__(256) void ball_query_kernel(
        const float* __restrict__ new_xyz) {
    int warp = (blockIdx.x * blockDim.x + threadIdx.x) >> 5;
    int lane = threadIdx.x & 31;
    if (warp >= B * M) return;

    int b = warp >> 12;
    const float nx = new_xyz[3 * warp + 0];
    const float ny = new_xyz[3 * warp + 1];
    const float nz = new_xyz[3 * warp + 2];
    const float sn = norm3_nofma(nx, ny, nz);

    const float4* __restrict__ P = g_xyz4 + b * N;
    int* __restrict__ ob = g_idx + warp * S;

    const unsigned FULL = 0xFFFFFFFFu;
    const unsigned lt   = (1u << lane) - 1u;
    int cnt = 0;
    int first = 0;

    for (int j0 = 0; j0 < N && cnt < S; j0 += 128) {
        float4 p0 = P[j0 + lane];
        float4 p1 = P[j0 + 32 + lane];
        float4 p2 = P[j0 + 64 + lane];
        float4 p3 = P[j0 + 96 + lane];
#pragma unroll
        for (int u = 0; u < 4; u++) {
            float4 p = (u == 0) ? p0 : (u == 1) ? p1 : (u == 2) ? p2 : p3;
            int j = j0 + u * 32 + lane;
            float dot = dot3_fma(nx, ny, nz, p.x, p.y, p.z);
            float d2  = __fmaf_rn(-2.0f, dot, __fadd_rn(sn, p.w));
            bool hit  = d2 < R2;
            unsigned mask = __ballot_sync(FULL, hit);
            if (mask) {
                int pos = cnt + __popc(mask & lt);
                if (hit && pos < S) ob[pos] = j;
                if (cnt == 0) first = __shfl_sync(FULL, j, __ffs(mask) - 1);
                cnt += __popc(mask);
            }
            if (cnt >= S) break;
        }
    }
    if (lane >= cnt) ob[lane] = first;
}

// ---------------- kernel 4: gather + concat, fully vectorized ----------------
// Phase 1: float4 row reads -> transposed scalar STS into padded tile.
// Phase 2: 4x LDS.32 (conflict-free) -> STG.128 (4x128B coalesced per warp).
__global__ __launch_bounds__(256) void gather_kernel(
        const float* __restrict__ xyz_embed,
        const float* __restrict__ new_xyz_embed,
        float* __restrict__ out) {
    __shared__ float  tile[NCH * TP];
    __shared__ int    sidx[S];
    __shared__ float4 ce4[E / 4];

    int center = blockIdx.x;            // b*M + m
    int b = center >> 12;
    int m = center & (M - 1);
    int tid = threadIdx.x;

    if (tid < S) sidx[tid] = g_idx[center * S + tid];
    if (tid < E / 4)
        ce4[tid] = ((const float4*)(new_xyz_embed + (size_t)center * E))[tid];
    __syncthreads();

    // --- embed: 32 points x 8 float4 = 256 items (exactly one pass) ---
    {
        int s = tid >> 3;               // point slot
        int q = tid & 7;                // float4 index within embed row
        int p = sidx[s];
        float4 v = ((const float4*)xyz_embed)[((size_t)b * N + p) * (E / 4) + q];
        float4 c = ce4[q];
        int ch = 4 * q;
        tile[(ch + 0) * TP + s] = v.x - c.x;
        tile[(ch + 1) * TP + s] = v.y - c.y;
        tile[(ch + 2) * TP + s] = v.z - c.z;
        tile[(ch + 3) * TP + s] = v.w - c.w;
    }
    // --- feat: 32 points x 16 float4 = 512 items (two passes) ---
#pragma unroll
    for (int t = tid; t < S * (C / 4); t += 256) {
        int s = t >> 4;
        int q = t & 15;
        int p = sidx[s];
        float4 v = ((const float4*)g_feat_t)[((size_t)b * N + p) * (C / 4) + q];
        int ch = E + 4 * q;
        tile[(ch + 0) * TP + s] = v.x;
        tile[(ch + 1) * TP + s] = v.y;
        tile[(ch + 2) * TP + s] = v.z;
        tile[(ch + 3) * TP + s] = v.w;
    }
    __syncthreads();

    // --- write: 96 channels x 8 float4 = 768 items (three passes) ---
    float4* out4 = (float4*)out;
#pragma unroll
    for (int t = tid; t < NCH * (S / 4); t += 256) {
        int ch = t >> 3;
        int s4 = t & 7;
        const float* r = tile + ch * TP + 4 * s4;
        float4 w = make_float4(r[0], r[1], r[2], r[3]);
        out4[(((size_t)b * NCH + ch) * M + m) * (S / 4) + s4] = w;
    }
}

// ---------------- launch -----------------------------------------------------
extern "C" void kernel_launch(void* const* d_in, const int* in_sizes, int n_in,
                              void* d_out, int out_size) {
    const float* xyz           = (const float*)d_in[0];
    const float* xyz_embed     = (const float*)d_in[1];
    const float* new_xyz       = (const float*)d_in[2];
    const float* new_xyz_embed = (const float*)d_in[3];
    const float* features      = (const float*)d_in[4];
    float* out = (float*)d_out;

    pack_xyz_kernel<<<(B * N + 255) / 256, 256>>>(xyz);
    transpose_feat_kernel<<<dim3(N / 32, C / 32, B), dim3(32, 8)>>>(features);
    ball_query_kernel<<<(B * M * 32 + 255) / 256, 256>>>(new_xyz);
    gather_kernel<<<B * M, 256>>>(xyz_embed, new_xyz_embed, out);
}

// round 9
// speedup vs baseline: 1.8496x; 1.4049x over previous
#include <cuda_runtime.h>
#include <cuda_bf16.h>
#include <cstdint>

#define B 2
#define N 16384
#define M 4096
#define E 32
#define C 64
#define S 32
#define NCH 96
#define R2 0.01f
#define TP 37
#define GC 10                 // grid cells per axis
#define NCELL (GC * GC * GC)  // 1000
#define CAP 128               // per-center hit buffer (mean ~68, 7sigma << 128)

// ---------------- scratch ----------------------------------------------------
__device__ float4 g_xyz4[B * N];                 // {x,y,z,norm} in index order (fallback path)
__device__ __align__(16) float g_feat_t[(size_t)B * N * C];
__device__ int    g_idx[B * M * S];
__device__ int    g_cnt[B * NCELL];
__device__ int    g_fill[B * NCELL];
__device__ int    g_cellStart[B * (NCELL + 1)];
__device__ float4 g_ptmp[B * N];                 // cell-scattered, unordered within cell
__device__ float4 g_pts[B * N];                  // cell-sorted, ascending index within cell
__device__ unsigned short g_slotcell[B * N];

// ---- frozen fp formulas (bit-exact vs XLA; do not touch) --------------------
__device__ __forceinline__ float norm3_nofma(float x, float y, float z) {
    return __fadd_rn(__fadd_rn(__fmul_rn(x, x), __fmul_rn(y, y)),
                     __fmul_rn(z, z));
}
__device__ __forceinline__ float dot3_fma(float ax, float ay, float az,
                                          float bx, float by, float bz) {
    return __fmaf_rn(az, bz, __fmaf_rn(ay, by, __fmul_rn(ax, bx)));
}
__device__ __forceinline__ int cell_of(float x, float y, float z) {
    int cx = min((int)(x * 10.0f), GC - 1);
    int cy = min((int)(y * 10.0f), GC - 1);
    int cz = min((int)(z * 10.0f), GC - 1);
    return (cz * GC + cy) * GC + cx;
}

// ---------------- prep: pack xyz (fallback path input) -----------------------
__global__ void pack_xyz_kernel(const float* __restrict__ xyz) {
    int i = blockIdx.x * blockDim.x + threadIdx.x;
    if (i < B * N) {
        float x = xyz[3 * i + 0], y = xyz[3 * i + 1], z = xyz[3 * i + 2];
        g_xyz4[i] = make_float4(x, y, z, norm3_nofma(x, y, z));
    }
}

// ---------------- prep: feature transpose (B,C,N)->(B,N,C) -------------------
__global__ void transpose_feat_kernel(const float* __restrict__ f) {
    __shared__ float t[32][33];
    int b  = blockIdx.z;
    int n0 = blockIdx.x * 32;
    int c0 = blockIdx.y * 32;
#pragma unroll
    for (int i = 0; i < 32; i += 8)
        t[threadIdx.y + i][threadIdx.x] =
            f[((size_t)(b * C + c0 + threadIdx.y + i)) * N + n0 + threadIdx.x];
    __syncthreads();
#pragma unroll
    for (int i = 0; i < 32; i += 8)
        g_feat_t[((size_t)b * N + n0 + threadIdx.y + i) * C + c0 + threadIdx.x] =
            t[threadIdx.x][threadIdx.y + i];
}

// ---------------- grid build -------------------------------------------------
__global__ void grid_zero_kernel() {
    int i = blockIdx.x * blockDim.x + threadIdx.x;
    if (i < B * NCELL) { g_cnt[i] = 0; g_fill[i] = 0; }
}

__global__ void grid_count_kernel(const float* __restrict__ xyz) {
    int i = blockIdx.x * blockDim.x + threadIdx.x;
    if (i < B * N) {
        int b = i >> 14;
        int c = cell_of(xyz[3 * i], xyz[3 * i + 1], xyz[3 * i + 2]);
        atomicAdd(&g_cnt[b * NCELL + c], 1);
    }
}

__global__ void grid_scan_kernel() {      // grid = B blocks of 1024 threads
    __shared__ int s[1024];
    int b = blockIdx.x, t = threadIdx.x;
    int val = (t < NCELL) ? g_cnt[b * NCELL + t] : 0;
    s[t] = val;
    __syncthreads();
    for (int off = 1; off < 1024; off <<= 1) {
        int x = (t >= off) ? s[t - off] : 0;
        __syncthreads();
        s[t] += x;
        __syncthreads();
    }
    if (t < NCELL) g_cellStart[b * (NCELL + 1) + t] = s[t] - val;  // exclusive
    if (t == NCELL - 1) g_cellStart[b * (NCELL + 1) + NCELL] = s[t];
}

__global__ void grid_scatter_kernel(const float* __restrict__ xyz) {
    int i = blockIdx.x * blockDim.x + threadIdx.x;
    if (i < B * N) {
        int b = i >> 14, p = i & (N - 1);
        float x = xyz[3 * i], y = xyz[3 * i + 1], z = xyz[3 * i + 2];
        int c = cell_of(x, y, z);
        int pos = g_cellStart[b * (NCELL + 1) + c] + atomicAdd(&g_fill[b * NCELL + c], 1);
        g_ptmp[b * N + pos] = make_float4(x, y, z, __int_as_float(p));
        g_slotcell[b * N + pos] = (unsigned short)c;
    }
}

// stabilize: within each cell order ascending by original index (deterministic)
__global__ void grid_rank_kernel() {
    int i = blockIdx.x * blockDim.x + threadIdx.x;
    if (i < B * N) {
        int b = i >> 14;
        int cell = g_slotcell[i];
        int s = g_cellStart[b * (NCELL + 1) + cell];
        int e = g_cellStart[b * (NCELL + 1) + cell + 1];
        float4 mine = g_ptmp[i];
        int my = __float_as_int(mine.w);
        int rank = 0;
        for (int q = s; q < e; q++)
            rank += (__float_as_int(g_ptmp[b * N + q].w) < my) ? 1 : 0;
        g_pts[b * N + s + rank] = mine;
    }
}

// ---------------- fallback: ordered linear scan (proven correct) -------------
__device__ __noinline__ void linear_scan_center(
        float nx, float ny, float nz, float sn, int b, int* ob, int lane) {
    const float4* __restrict__ P = g_xyz4 + b * N;
    const unsigned FULL = 0xFFFFFFFFu;
    const unsigned lt = (1u << lane) - 1u;
    int cnt = 0, first = 0;
    for (int j0 = 0; j0 < N && cnt < S; j0 += 32) {
        float4 p = P[j0 + lane];
        int j = j0 + lane;
        float dot = dot3_fma(nx, ny, nz, p.x, p.y, p.z);
        float d2  = __fmaf_rn(-2.0f, dot, __fadd_rn(sn, p.w));
        bool hit  = d2 < R2;
        unsigned mask = __ballot_sync(FULL, hit);
        if (mask) {
            int pos = cnt + __popc(mask & lt);
            if (hit && pos < S) ob[pos] = j;
            if (cnt == 0) first = __shfl_sync(FULL, j, __ffs(mask) - 1);
            cnt += __popc(mask);
        }
    }
    if (lane >= cnt) ob[lane] = first;
}

// ---------------- ball query via grid (warp per center) ----------------------
__global__ __launch_bounds__(256) void ball_query_grid_kernel(
        const float* __restrict__ new_xyz) {
    __shared__ int buf[8][CAP];
    int gw   = (blockIdx.x * blockDim.x + threadIdx.x) >> 5;
    int w    = threadIdx.x >> 5;
    int lane = threadIdx.x & 31;
    if (gw >= B * M) return;

    int b = gw >> 12;
    const float nx = new_xyz[3 * gw + 0];
    const float ny = new_xyz[3 * gw + 1];
    const float nz = new_xyz[3 * gw + 2];
    const float sn = norm3_nofma(nx, ny, nz);

    const float4* __restrict__ P = g_pts + b * N;
    const int* __restrict__ cs = g_cellStart + b * (NCELL + 1);
    int* __restrict__ ob = g_idx + gw * S;

    const unsigned FULL = 0xFFFFFFFFu;
    const unsigned lt = (1u << lane) - 1u;

    // conservative cell window (slack 1e-3 in coords >> 1e-6 fp error band)
    int x0 = max(0, (int)floorf((nx - 0.1001f) * 10.f));
    int x1 = min(GC - 1, (int)floorf((nx + 0.1001f) * 10.f));
    int y0 = max(0, (int)floorf((ny - 0.1001f) * 10.f));
    int y1 = min(GC - 1, (int)floorf((ny + 0.1001f) * 10.f));
    int z0 = max(0, (int)floorf((nz - 0.1001f) * 10.f));
    int z1 = min(GC - 1, (int)floorf((nz + 0.1001f) * 10.f));

    int cnt = 0;
    for (int gz = z0; gz <= z1; gz++) {
        float dz = fmaxf(fmaxf(0.1f * gz - nz, nz - 0.1f * (gz + 1)), 0.f);
        for (int gy = y0; gy <= y1; gy++) {
            float dy = fmaxf(fmaxf(0.1f * gy - ny, ny - 0.1f * (gy + 1)), 0.f);
            if (__fmaf_rn(dy, dy, dz * dz) > R2 + 2e-4f) continue;  // conservative prune
            int base = (gz * GC + gy) * GC;
            int sS = cs[base + x0];
            int sE = cs[base + x1 + 1];
            for (int p0 = sS; p0 < sE; p0 += 32) {
                int pi = p0 + lane;
                bool valid = pi < sE;
                float4 pt = valid ? P[pi] : make_float4(9.f, 9.f, 9.f, 0.f);
                float sp  = norm3_nofma(pt.x, pt.y, pt.z);
                float dot = dot3_fma(nx, ny, nz, pt.x, pt.y, pt.z);
                float d2  = __fmaf_rn(-2.0f, dot, __fadd_rn(sn, sp));
                bool hit  = valid && (d2 < R2);
                unsigned mask = __ballot_sync(FULL, hit);
                if (mask) {
                    int pos = cnt + __popc(mask & lt);
                    if (hit && pos < CAP) buf[w][pos] = __float_as_int(pt.w);
                    cnt += __popc(mask);
                }
            }
        }
    }
    __syncwarp();

    if (cnt > CAP) {  // overflow (astronomically rare): bulletproof fallback
        linear_scan_center(nx, ny, nz, sn, b, ob, lane);
        return;
    }

    // ---- warp bitonic sort of 128 keys (4 regs/lane), ascending -------------
    int v[4];
#pragma unroll
    for (int r = 0; r < 4; r++) {
        int t = r * 32 + lane;
        v[r] = (t < cnt) ? buf[w][t] : 0x7FFFFFFF;
    }
#pragma unroll
    for (int k = 2; k <= 128; k <<= 1) {
#pragma unroll
        for (int j = 64; j > 0; j >>= 1) {
            if (j >= k) continue;
            if (j >= 32) {
                int jr = j >> 5;
#pragma unroll
                for (int r = 0; r < 4; r++) {
                    if ((r & jr) == 0) {
                        int r2 = r | jr;
                        bool up = (((r * 32) & k) == 0);
                        int a = v[r], c = v[r2];
                        int lo = min(a, c), hi = max(a, c);
                        v[r]  = up ? lo : hi;
                        v[r2] = up ? hi : lo;
                    }
                }
            } else {
#pragma unroll
                for (int r = 0; r < 4; r++) {
                    int other = __shfl_xor_sync(FULL, v[r], j);
                    bool up = (((r * 32 + lane) & k) == 0);
                    bool lower = ((lane & j) == 0);
                    v[r] = (up == lower) ? min(v[r], other) : max(v[r], other);
                }
            }
        }
    }

    int my = v[0];                          // sorted positions 0..31
    int first = __shfl_sync(FULL, my, 0);
    if (cnt == 0) first = 0;
    ob[lane] = (lane < cnt) ? my : first;
}

// ---------------- gather + concat (unchanged from R3) ------------------------
__global__ __launch_bounds__(256) void gather_kernel(
        const float* __restrict__ xyz_embed,
        const float* __restrict__ new_xyz_embed,
        float* __restrict__ out) {
    __shared__ float  tile[NCH * TP];
    __shared__ int    sidx[S];
    __shared__ float4 ce4[E / 4];

    int center = blockIdx.x;
    int b = center >> 12;
    int m = center & (M - 1);
    int tid = threadIdx.x;

    if (tid < S) sidx[tid] = g_idx[center * S + tid];
    if (tid < E / 4)
        ce4[tid] = ((const float4*)(new_xyz_embed + (size_t)center * E))[tid];
    __syncthreads();

    {
        int s = tid >> 3;
        int q = tid & 7;
        int p = sidx[s];
        float4 v = ((const float4*)xyz_embed)[((size_t)b * N + p) * (E / 4) + q];
        float4 c = ce4[q];
        int ch = 4 * q;
        tile[(ch + 0) * TP + s] = v.x - c.x;
        tile[(ch + 1) * TP + s] = v.y - c.y;
        tile[(ch + 2) * TP + s] = v.z - c.z;
        tile[(ch + 3) * TP + s] = v.w - c.w;
    }
#pragma unroll
    for (int t = tid; t < S * (C / 4); t += 256) {
        int s = t >> 4;
        int q = t & 15;
        int p = sidx[s];
        float4 v = ((const float4*)g_feat_t)[((size_t)b * N + p) * (C / 4) + q];
        int ch = E + 4 * q;
        tile[(ch + 0) * TP + s] = v.x;
        tile[(ch + 1) * TP + s] = v.y;
        tile[(ch + 2) * TP + s] = v.z;
        tile[(ch + 3) * TP + s] = v.w;
    }
    __syncthreads();

    float4* out4 = (float4*)out;
#pragma unroll
    for (int t = tid; t < NCH * (S / 4); t += 256) {
        int ch = t >> 3;
        int s4 = t & 7;
        const float* r = tile + ch * TP + 4 * s4;
        out4[(((size_t)b * NCH + ch) * M + m) * (S / 4) + s4] =
            make_float4(r[0], r[1], r[2], r[3]);
    }
}

// ---------------- launch -----------------------------------------------------
extern "C" void kernel_launch(void* const* d_in, const int* in_sizes, int n_in,
                              void* d_out, int out_size) {
    const float* xyz           = (const float*)d_in[0];
    const float* xyz_embed     = (const float*)d_in[1];
    const float* new_xyz       = (const float*)d_in[2];
    const float* new_xyz_embed = (const float*)d_in[3];
    const float* features      = (const float*)d_in[4];
    float* out = (float*)d_out;

    pack_xyz_kernel<<<(B * N + 255) / 256, 256>>>(xyz);
    grid_zero_kernel<<<(B * NCELL + 255) / 256, 256>>>();
    transpose_feat_kernel<<<dim3(N / 32, C / 32, B), dim3(32, 8)>>>(features);
    grid_count_kernel<<<(B * N + 255) / 256, 256>>>(xyz);
    grid_scan_kernel<<<B, 1024>>>();
    grid_scatter_kernel<<<(B * N + 255) / 256, 256>>>(xyz);
    grid_rank_kernel<<<(B * N + 255) / 256, 256>>>();
    ball_query_grid_kernel<<<(B * M * 32 + 255) / 256, 256>>>(new_xyz);
    gather_kernel<<<B * M, 256>>>(xyz_embed, new_xyz_embed, out);
}

// round 10
// speedup vs baseline: 1.8673x; 1.0096x over previous
#include <cuda_runtime.h>
#include <cuda_bf16.h>
#include <cstdint>

#define B 2
#define N 16384
#define M 4096
#define E 32
#define C 64
#define S 32
#define NCH 96
#define R2 0.01f
#define TP 37
#define GC 10
#define NCELL (GC * GC * GC)
#define CAP 128

// ---------------- scratch ----------------------------------------------------
__device__ float4 g_xyz4[B * N];                 // {x,y,z,norm} index order
__device__ __align__(16) float g_feat_t[(size_t)B * N * C];
__device__ int    g_idx[B * M * S];
__device__ int    g_cnt[B * NCELL];
__device__ int    g_fill[B * NCELL];
__device__ int    g_cellStart[B * (NCELL + 1)];
__device__ float4 g_ptmp[B * N];                 // cell-scattered {x,y,z,idx}
__device__ float4 g_pts[B * N];                  // cell-sorted by index

// ---- frozen fp formulas (bit-exact vs XLA; do not touch) --------------------
__device__ __forceinline__ float norm3_nofma(float x, float y, float z) {
    return __fadd_rn(__fadd_rn(__fmul_rn(x, x), __fmul_rn(y, y)),
                     __fmul_rn(z, z));
}
__device__ __forceinline__ float dot3_fma(float ax, float ay, float az,
                                          float bx, float by, float bz) {
    return __fmaf_rn(az, bz, __fmaf_rn(ay, by, __fmul_rn(ax, bx)));
}
__device__ __forceinline__ int cell_of(float x, float y, float z) {
    int cx = min((int)(x * 10.0f), GC - 1);
    int cy = min((int)(y * 10.0f), GC - 1);
    int cz = min((int)(z * 10.0f), GC - 1);
    return (cz * GC + cy) * GC + cx;
}

// ---------------- prep: pack xyz + zero grid counters ------------------------
__global__ void pack_zero_kernel(const float* __restrict__ xyz) {
    int i = blockIdx.x * blockDim.x + threadIdx.x;
    if (i < B * N) {
        float x = xyz[3 * i + 0], y = xyz[3 * i + 1], z = xyz[3 * i + 2];
        g_xyz4[i] = make_float4(x, y, z, norm3_nofma(x, y, z));
    }
    if (i < B * NCELL) { g_cnt[i] = 0; g_fill[i] = 0; }
}

// ---------------- prep: feature transpose (B,C,N)->(B,N,C) -------------------
__global__ void transpose_feat_kernel(const float* __restrict__ f) {
    __shared__ float t[32][33];
    int b  = blockIdx.z;
    int n0 = blockIdx.x * 32;
    int c0 = blockIdx.y * 32;
#pragma unroll
    for (int i = 0; i < 32; i += 8)
        t[threadIdx.y + i][threadIdx.x] =
            f[((size_t)(b * C + c0 + threadIdx.y + i)) * N + n0 + threadIdx.x];
    __syncthreads();
#pragma unroll
    for (int i = 0; i < 32; i += 8)
        g_feat_t[((size_t)b * N + n0 + threadIdx.y + i) * C + c0 + threadIdx.x] =
            t[threadIdx.x][threadIdx.y + i];
}

// ---------------- grid build (reads packed g_xyz4: LDG.128) ------------------
__global__ void grid_count_kernel() {
    int i = blockIdx.x * blockDim.x + threadIdx.x;
    if (i < B * N) {
        int b = i >> 14;
        float4 p = g_xyz4[i];
        atomicAdd(&g_cnt[b * NCELL + cell_of(p.x, p.y, p.z)], 1);
    }
}

__global__ void grid_scan_kernel() {      // grid = B blocks of 1024 threads
    __shared__ int s[1024];
    int b = blockIdx.x, t = threadIdx.x;
    int val = (t < NCELL) ? g_cnt[b * NCELL + t] : 0;
    s[t] = val;
    __syncthreads();
    for (int off = 1; off < 1024; off <<= 1) {
        int x = (t >= off) ? s[t - off] : 0;
        __syncthreads();
        s[t] += x;
        __syncthreads();
    }
    if (t < NCELL) g_cellStart[b * (NCELL + 1) + t] = s[t] - val;
    if (t == NCELL - 1) g_cellStart[b * (NCELL + 1) + NCELL] = s[t];
}

__global__ void grid_scatter_kernel() {
    int i = blockIdx.x * blockDim.x + threadIdx.x;
    if (i < B * N) {
        int b = i >> 14, p = i & (N - 1);
        float4 q = g_xyz4[i];
        int c = cell_of(q.x, q.y, q.z);
        int pos = g_cellStart[b * (NCELL + 1) + c] + atomicAdd(&g_fill[b * NCELL + c], 1);
        g_ptmp[b * N + pos] = make_float4(q.x, q.y, q.z, __int_as_float(p));
    }
}

// stabilize: within each cell, ascending original index (deterministic)
__global__ void grid_rank_kernel() {
    int i = blockIdx.x * blockDim.x + threadIdx.x;
    if (i < B * N) {
        int b = i >> 14;
        float4 mine = g_ptmp[i];
        int cell = cell_of(mine.x, mine.y, mine.z);
        int s = g_cellStart[b * (NCELL + 1) + cell];
        int e = g_cellStart[b * (NCELL + 1) + cell + 1];
        int my = __float_as_int(mine.w);
        int rank = 0;
        for (int q = s; q < e; q++)
            rank += (__float_as_int(g_ptmp[b * N + q].w) < my) ? 1 : 0;
        g_pts[b * N + s + rank] = mine;
    }
}

// ---------------- fallback: ordered linear scan (proven correct) -------------
__device__ __noinline__ void linear_scan_center(
        float nx, float ny, float nz, float sn, int b, int* ob, int lane) {
    const float4* __restrict__ P = g_xyz4 + b * N;
    const unsigned FULL = 0xFFFFFFFFu;
    const unsigned lt = (1u << lane) - 1u;
    int cnt = 0, first = 0;
    for (int j0 = 0; j0 < N && cnt < S; j0 += 32) {
        float4 p = P[j0 + lane];
        int j = j0 + lane;
        float dot = dot3_fma(nx, ny, nz, p.x, p.y, p.z);
        float d2  = __fmaf_rn(-2.0f, dot, __fadd_rn(sn, p.w));
        bool hit  = d2 < R2;
        unsigned mask = __ballot_sync(FULL, hit);
        if (mask) {
            int pos = cnt + __popc(mask & lt);
            if (hit && pos < S) ob[pos] = j;
            if (cnt == 0) first = __shfl_sync(FULL, j, __ffs(mask) - 1);
            cnt += __popc(mask);
        }
    }
    if (lane >= cnt) ob[lane] = first;
}

// ---- generalized warp bitonic sort: NR*32 keys, NR regs/lane, ascending -----
template <int NR>
__device__ __forceinline__ void bitonic_sort_warp(int (&v)[NR], int lane) {
    const unsigned FULL = 0xFFFFFFFFu;
#pragma unroll
    for (int k = 2; k <= NR * 32; k <<= 1) {
#pragma unroll
        for (int j = NR * 16; j > 0; j >>= 1) {
            if (j >= k) continue;
            if (j >= 32) {               // cross-register (k >= 64 here)
                int jr = j >> 5;
#pragma unroll
                for (int r = 0; r < NR; r++) {
                    if ((r & jr) == 0) {
                        int r2 = r | jr;
                        bool up = (((r * 32) & k) == 0);
                        int a = v[r], c = v[r2];
                        int lo = min(a, c), hi = max(a, c);
                        v[r]  = up ? lo : hi;
                        v[r2] = up ? hi : lo;
                    }
                }
            } else {
#pragma unroll
                for (int r = 0; r < NR; r++) {
                    int other = __shfl_xor_sync(FULL, v[r], j);
                    bool up = (((r * 32 + lane) & k) == 0);
                    bool lower = ((lane & j) == 0);
                    v[r] = (up == lower) ? min(v[r], other) : max(v[r], other);
                }
            }
        }
    }
}

template <int NR>
__device__ __forceinline__ void sort_emit(const int* bufw, int cnt, int lane,
                                          int* ob) {
    int v[NR];
#pragma unroll
    for (int r = 0; r < NR; r++) {
        int t = r * 32 + lane;
        v[r] = (t < cnt) ? bufw[t] : 0x7FFFFFFF;
    }
    bitonic_sort_warp<NR>(v, lane);
    int my = v[0];
    int first = __shfl_sync(0xFFFFFFFFu, my, 0);
    if (cnt == 0) first = 0;
    ob[lane] = (lane < cnt) ? my : first;
}

// ---------------- ball query via grid (warp per center) ----------------------
__global__ __launch_bounds__(256) void ball_query_grid_kernel(
        const float* __restrict__ new_xyz) {
    __shared__ int buf[8][CAP];
    int gw   = (blockIdx.x * blockDim.x + threadIdx.x) >> 5;
    int w    = threadIdx.x >> 5;
    int lane = threadIdx.x & 31;
    if (gw >= B * M) return;

    int b = gw >> 12;
    const float nx = new_xyz[3 * gw + 0];
    const float ny = new_xyz[3 * gw + 1];
    const float nz = new_xyz[3 * gw + 2];
    const float sn = norm3_nofma(nx, ny, nz);

    const float4* __restrict__ P = g_pts + b * N;
    const int* __restrict__ cs = g_cellStart + b * (NCELL + 1);
    int* __restrict__ ob = g_idx + gw * S;

    const unsigned FULL = 0xFFFFFFFFu;
    const unsigned lt = (1u << lane) - 1u;

    int x0 = max(0, (int)floorf((nx - 0.1001f) * 10.f));
    int x1 = min(GC - 1, (int)floorf((nx + 0.1001f) * 10.f));
    int y0 = max(0, (int)floorf((ny - 0.1001f) * 10.f));
    int y1 = min(GC - 1, (int)floorf((ny + 0.1001f) * 10.f));
    int z0 = max(0, (int)floorf((nz - 0.1001f) * 10.f));
    int z1 = min(GC - 1, (int)floorf((nz + 0.1001f) * 10.f));

    int cnt = 0;
    for (int gz = z0; gz <= z1; gz++) {
        float dz = fmaxf(fmaxf(0.1f * gz - nz, nz - 0.1f * (gz + 1)), 0.f);
        for (int gy = y0; gy <= y1; gy++) {
            float dy = fmaxf(fmaxf(0.1f * gy - ny, ny - 0.1f * (gy + 1)), 0.f);
            if (__fmaf_rn(dy, dy, dz * dz) > R2 + 2e-4f) continue;
            int base = (gz * GC + gy) * GC;
            int sS = cs[base + x0];
            int sE = cs[base + x1 + 1];
            for (int p0 = sS; p0 < sE; p0 += 32) {
                int pi = p0 + lane;
                bool valid = pi < sE;
                float4 pt = valid ? P[pi] : make_float4(9.f, 9.f, 9.f, 0.f);
                float sp  = norm3_nofma(pt.x, pt.y, pt.z);
                float dot = dot3_fma(nx, ny, nz, pt.x, pt.y, pt.z);
                float d2  = __fmaf_rn(-2.0f, dot, __fadd_rn(sn, sp));
                bool hit  = valid && (d2 < R2);
                unsigned mask = __ballot_sync(FULL, hit);
                if (mask) {
                    int pos = cnt + __popc(mask & lt);
                    if (hit && pos < CAP) buf[w][pos] = __float_as_int(pt.w);
                    cnt += __popc(mask);
                }
            }
        }
    }
    __syncwarp();

    if (cnt > CAP) {                     // astronomically rare: proven fallback
        linear_scan_center(nx, ny, nz, sn, b, ob, lane);
        return;
    }
    // adaptive sort width (cnt is warp-uniform -> no divergence)
    if (cnt <= 32)      sort_emit<1>(buf[w], cnt, lane, ob);
    else if (cnt <= 64) sort_emit<2>(buf[w], cnt, lane, ob);
    else                sort_emit<4>(buf[w], cnt, lane, ob);
}

// ---------------- gather + concat (frozen from R3) ---------------------------
__global__ __launch_bounds__(256) void gather_kernel(
        const float* __restrict__ xyz_embed,
        const float* __restrict__ new_xyz_embed,
        float* __restrict__ out) {
    __shared__ float  tile[NCH * TP];
    __shared__ int    sidx[S];
    __shared__ float4 ce4[E / 4];

    int center = blockIdx.x;
    int b = center >> 12;
    int m = center & (M - 1);
    int tid = threadIdx.x;

    if (tid < S) sidx[tid] = g_idx[center * S + tid];
    if (tid < E / 4)
        ce4[tid] = ((const float4*)(new_xyz_embed + (size_t)center * E))[tid];
    __syncthreads();

    {
        int s = tid >> 3;
        int q = tid & 7;
        int p = sidx[s];
        float4 v = ((const float4*)xyz_embed)[((size_t)b * N + p) * (E / 4) + q];
        float4 c = ce4[q];
        int ch = 4 * q;
        tile[(ch + 0) * TP + s] = v.x - c.x;
        tile[(ch + 1) * TP + s] = v.y - c.y;
        tile[(ch + 2) * TP + s] = v.z - c.z;
        tile[(ch + 3) * TP + s] = v.w - c.w;
    }
#pragma unroll
    for (int t = tid; t < S * (C / 4); t += 256) {
        int s = t >> 4;
        int q = t & 15;
        int p = sidx[s];
        float4 v = ((const float4*)g_feat_t)[((size_t)b * N + p) * (C / 4) + q];
        int ch = E + 4 * q;
        tile[(ch + 0) * TP + s] = v.x;
        tile[(ch + 1) * TP + s] = v.y;
        tile[(ch + 2) * TP + s] = v.z;
        tile[(ch + 3) * TP + s] = v.w;
    }
    __syncthreads();

    float4* out4 = (float4*)out;
#pragma unroll
    for (int t = tid; t < NCH * (S / 4); t += 256) {
        int ch = t >> 3;
        int s4 = t & 7;
        const float* r = tile + ch * TP + 4 * s4;
        out4[(((size_t)b * NCH + ch) * M + m) * (S / 4) + s4] =
            make_float4(r[0], r[1], r[2], r[3]);
    }
}

// ---------------- launch -----------------------------------------------------
extern "C" void kernel_launch(void* const* d_in, const int* in_sizes, int n_in,
                              void* d_out, int out_size) {
    const float* xyz           = (const float*)d_in[0];
    const float* xyz_embed     = (const float*)d_in[1];
    const float* new_xyz_embed = (const float*)d_in[3];
    const float* new_xyz       = (const float*)d_in[2];
    const float* features      = (const float*)d_in[4];
    float* out = (float*)d_out;

    pack_zero_kernel<<<(B * N + 255) / 256, 256>>>(xyz);
    transpose_feat_kernel<<<dim3(N / 32, C / 32, B), dim3(32, 8)>>>(features);
    grid_count_kernel<<<(B * N + 255) / 256, 256>>>();
    grid_scan_kernel<<<B, 1024>>>();
    grid_scatter_kernel<<<(B * N + 255) / 256, 256>>>();
    grid_rank_kernel<<<(B * N + 255) / 256, 256>>>();
    ball_query_grid_kernel<<<(B * M * 32 + 255) / 256, 256>>>(new_xyz);
    gather_kernel<<<B * M, 256>>>(xyz_embed, new_xyz_embed, out);
}

// round 13
// speedup vs baseline: 2.1211x; 1.1359x over previous
#include <cuda_runtime.h>
#include <cuda_bf16.h>
#include <cstdint>

#define B 2
#define N 16384
#define M 4096
#define E 32
#define C 64
#define S 32
#define NCH 96
#define R2 0.01f
#define TP 37
#define GC 10
#define NCELL (GC * GC * GC)
#define CAP 128

// ---------------- scratch ----------------------------------------------------
__device__ float4 g_xyz4[B * N];                 // {x,y,z,norm} index order
__device__ __align__(16) float g_feat_t[(size_t)B * N * C];
__device__ int    g_cnt[B * NCELL];
__device__ int    g_fill[B * NCELL];
__device__ int    g_cellStart[B * (NCELL + 1)];
__device__ float4 g_ptmp[B * N];                 // cell-bucketed {x,y,z,idx} (order within cell irrelevant)

// ---- frozen fp formulas (bit-exact vs XLA; do not touch) --------------------
__device__ __forceinline__ float norm3_nofma(float x, float y, float z) {
    return __fadd_rn(__fadd_rn(__fmul_rn(x, x), __fmul_rn(y, y)),
                     __fmul_rn(z, z));
}
__device__ __forceinline__ float dot3_fma(float ax, float ay, float az,
                                          float bx, float by, float bz) {
    return __fmaf_rn(az, bz, __fmaf_rn(ay, by, __fmul_rn(ax, bx)));
}
__device__ __forceinline__ int cell_of(float x, float y, float z) {
    int cx = min((int)(x * 10.0f), GC - 1);
    int cy = min((int)(y * 10.0f), GC - 1);
    int cz = min((int)(z * 10.0f), GC - 1);
    return (cz * GC + cy) * GC + cx;
}

// ------ K1: fused pack xyz (+zero counters) and feature transpose ------------
// blocks [0,128): pack+zero.  blocks [128, 128+2048): 32x32 transpose tiles.
__global__ __launch_bounds__(256) void prep_kernel(
        const float* __restrict__ xyz, const float* __restrict__ f) {
    if (blockIdx.x < 128) {
        int i = blockIdx.x * 256 + threadIdx.x;
        if (i < B * N) {
            float x = xyz[3 * i + 0], y = xyz[3 * i + 1], z = xyz[3 * i + 2];
            g_xyz4[i] = make_float4(x, y, z, norm3_nofma(x, y, z));
        }
        if (i < B * NCELL) { g_cnt[i] = 0; g_fill[i] = 0; }
    } else {
        __shared__ float t[32][33];
        int bi = blockIdx.x - 128;
        int n0 = (bi & 511) * 32;
        int c0 = ((bi >> 9) & 1) * 32;
        int b  = bi >> 10;
        int tx = threadIdx.x & 31, ty = threadIdx.x >> 5;
#pragma unroll
        for (int i = 0; i < 32; i += 8)
            t[ty + i][tx] = f[((size_t)(b * C + c0 + ty + i)) * N + n0 + tx];
        __syncthreads();
#pragma unroll
        for (int i = 0; i < 32; i += 8)
            g_feat_t[((size_t)b * N + n0 + ty + i) * C + c0 + tx] = t[tx][ty + i];
    }
}

// ------ K2: grid count (reads packed g_xyz4: LDG.128) ------------------------
__global__ void grid_count_kernel() {
    int i = blockIdx.x * blockDim.x + threadIdx.x;
    if (i < B * N) {
        int b = i >> 14;
        float4 p = g_xyz4[i];
        atomicAdd(&g_cnt[b * NCELL + cell_of(p.x, p.y, p.z)], 1);
    }
}

// ------ K3: exclusive scan of cell counts (warp-shuffle, 2 barriers) ---------
__global__ void grid_scan_kernel() {      // grid = B blocks of 1024
    __shared__ int ws[32];
    int b = blockIdx.x, t = threadIdx.x;
    int lane = t & 31, wid = t >> 5;
    int val = (t < NCELL) ? g_cnt[b * NCELL + t] : 0;
    int x = val;
#pragma unroll
    for (int o = 1; o < 32; o <<= 1) {
        int y = __shfl_up_sync(0xFFFFFFFFu, x, o);
        if (lane >= o) x += y;
    }
    if (lane == 31) ws[wid] = x;
    __syncthreads();
    if (wid == 0) {
        int z = ws[lane];
#pragma unroll
        for (int o = 1; o < 32; o <<= 1) {
            int y = __shfl_up_sync(0xFFFFFFFFu, z, o);
            if (lane >= o) z += y;
        }
        ws[lane] = z;
    }
    __syncthreads();
    int incl = x + (wid > 0 ? ws[wid - 1] : 0);
    if (t < NCELL) g_cellStart[b * (NCELL + 1) + t] = incl - val;
    if (t == NCELL - 1) g_cellStart[b * (NCELL + 1) + NCELL] = incl;
}

// ------ K4: scatter points into cell buckets (order within cell: any) --------
__global__ void grid_scatter_kernel() {
    int i = blockIdx.x * blockDim.x + threadIdx.x;
    if (i < B * N) {
        int b = i >> 14, p = i & (N - 1);
        float4 q = g_xyz4[i];
        int c = cell_of(q.x, q.y, q.z);
        int pos = g_cellStart[b * (NCELL + 1) + c] + atomicAdd(&g_fill[b * NCELL + c], 1);
        g_ptmp[b * N + pos] = make_float4(q.x, q.y, q.z, __int_as_float(p));
    }
}

// ---------------- fallback: ordered linear scan (proven correct) -------------
__device__ __noinline__ void linear_scan_center(
        float nx, float ny, float nz, float sn, int b, int* ob, int lane) {
    const float4* __restrict__ P = g_xyz4 + b * N;
    const unsigned FULL = 0xFFFFFFFFu;
    const unsigned lt = (1u << lane) - 1u;
    int cnt = 0, first = 0;
    for (int j0 = 0; j0 < N && cnt < S; j0 += 32) {
        float4 p = P[j0 + lane];
        int j = j0 + lane;
        float dot = dot3_fma(nx, ny, nz, p.x, p.y, p.z);
        float d2  = __fmaf_rn(-2.0f, dot, __fadd_rn(sn, p.w));
        bool hit  = d2 < R2;
        unsigned mask = __ballot_sync(FULL, hit);
        if (mask) {
            int pos = cnt + __popc(mask & lt);
            if (hit && pos < S) ob[pos] = j;
            if (cnt == 0) first = __shfl_sync(FULL, j, __ffs(mask) - 1);
            cnt += __popc(mask);
        }
    }
    if (lane >= cnt) ob[lane] = first;
}

// ---- generalized warp bitonic sort: NR*32 keys, NR regs/lane, ascending -----
template <int NR>
__device__ __forceinline__ void bitonic_sort_warp(int (&v)[NR], int lane) {
    const unsigned FULL = 0xFFFFFFFFu;
#pragma unroll
    for (int k = 2; k <= NR * 32; k <<= 1) {
#pragma unroll
        for (int j = NR * 16; j > 0; j >>= 1) {
            if (j >= k) continue;
            if (j >= 32) {               // cross-register (k >= 64 here)
                int jr = j >> 5;
#pragma unroll
                for (int r = 0; r < NR; r++) {
                    if ((r & jr) == 0) {
                        int r2 = r | jr;
                        bool up = (((r * 32) & k) == 0);
                        int a = v[r], c = v[r2];
                        int lo = min(a, c), hi = max(a, c);
                        v[r]  = up ? lo : hi;
                        v[r2] = up ? hi : lo;
                    }
                }
            } else {
#pragma unroll
                for (int r = 0; r < NR; r++) {
                    int other = __shfl_xor_sync(FULL, v[r], j);
                    bool up = (((r * 32 + lane) & k) == 0);
                    bool lower = ((lane & j) == 0);
                    v[r] = (up == lower) ? min(v[r], other) : max(v[r], other);
                }
            }
        }
    }
}

template <int NR>
__device__ __forceinline__ void sort_emit(const int* bufw, int cnt, int lane,
                                          int* ob) {
    int v[NR];
#pragma unroll
    for (int r = 0; r < NR; r++) {
        int t = r * 32 + lane;
        v[r] = (t < cnt) ? bufw[t] : 0x7FFFFFFF;
    }
    bitonic_sort_warp<NR>(v, lane);
    int my = v[0];
    int first = __shfl_sync(0xFFFFFFFFu, my, 0);
    if (cnt == 0) first = 0;
    ob[lane] = (lane < cnt) ? my : first;
}

// ------ K5: fused ball query (warp/center) + gather (block/8 centers) --------
__global__ __launch_bounds__(256) void query_gather_kernel(
        const float* __restrict__ new_xyz,
        const float* __restrict__ xyz_embed,
        const float* __restrict__ new_xyz_embed,
        float* __restrict__ out) {
    __shared__ int   buf[8][CAP];
    __shared__ int   sidx[8][S];
    __shared__ float tile[NCH * TP];

    int w    = threadIdx.x >> 5;
    int lane = threadIdx.x & 31;
    int tid  = threadIdx.x;
    int gw   = blockIdx.x * 8 + w;        // this warp's center
    const unsigned FULL = 0xFFFFFFFFu;
    const unsigned lt   = (1u << lane) - 1u;

    // ================= query phase (warp per center) =================
    {
        int b = gw >> 12;
        const float nx = new_xyz[3 * gw + 0];
        const float ny = new_xyz[3 * gw + 1];
        const float nz = new_xyz[3 * gw + 2];
        const float sn = norm3_nofma(nx, ny, nz);

        const float4* __restrict__ P = g_ptmp + b * N;
        const int* __restrict__ cs = g_cellStart + b * (NCELL + 1);

        int x0 = max(0, (int)floorf((nx - 0.1001f) * 10.f));
        int x1 = min(GC - 1, (int)floorf((nx + 0.1001f) * 10.f));
        int y0 = max(0, (int)floorf((ny - 0.1001f) * 10.f));
        int y1 = min(GC - 1, (int)floorf((ny + 0.1001f) * 10.f));
        int z0 = max(0, (int)floorf((nz - 0.1001f) * 10.f));
        int z1 = min(GC - 1, (int)floorf((nz + 0.1001f) * 10.f));

        int cnt = 0;
        for (int gz = z0; gz <= z1; gz++) {
            float dz = fmaxf(fmaxf(0.1f * gz - nz, nz - 0.1f * (gz + 1)), 0.f);
            for (int gy = y0; gy <= y1; gy++) {
                float dy = fmaxf(fmaxf(0.1f * gy - ny, ny - 0.1f * (gy + 1)), 0.f);
                if (__fmaf_rn(dy, dy, dz * dz) > R2 + 2e-4f) continue;
                int base = (gz * GC + gy) * GC;
                int sS = cs[base + x0];
                int sE = cs[base + x1 + 1];
                for (int p0 = sS; p0 < sE; p0 += 32) {
                    int pi = p0 + lane;
                    bool valid = pi < sE;
                    float4 pt = valid ? P[pi] : make_float4(9.f, 9.f, 9.f, 0.f);
                    float sp  = norm3_nofma(pt.x, pt.y, pt.z);
                    float dot = dot3_fma(nx, ny, nz, pt.x, pt.y, pt.z);
                    float d2  = __fmaf_rn(-2.0f, dot, __fadd_rn(sn, sp));
                    bool hit  = valid && (d2 < R2);
                    unsigned mask = __ballot_sync(FULL, hit);
                    if (mask) {
                        int pos = cnt + __popc(mask & lt);
                        if (hit && pos < CAP) buf[w][pos] = __float_as_int(pt.w);
                        cnt += __popc(mask);
                    }
                }
            }
        }
        __syncwarp();

        if (cnt > CAP) {                 // astronomically rare: proven fallback
            linear_scan_center(nx, ny, nz, sn, b, sidx[w], lane);
        } else if (cnt <= 32) {
            sort_emit<1>(buf[w], cnt, lane, sidx[w]);
        } else if (cnt <= 64) {
            sort_emit<2>(buf[w], cnt, lane, sidx[w]);
        } else {
            sort_emit<4>(buf[w], cnt, lane, sidx[w]);
        }
    }
    __syncthreads();

    // ================= gather phase (block per center, 8 iterations) =========
#pragma unroll 1
    for (int c8 = 0; c8 < 8; c8++) {
        int center = blockIdx.x * 8 + c8;
        int b = center >> 12;
        int m = center & (M - 1);

        // embed: 32 points x 8 float4 (one pass)
        {
            int s = tid >> 3;
            int q = tid & 7;
            int p = sidx[c8][s];
            float4 v = ((const float4*)xyz_embed)[((size_t)b * N + p) * (E / 4) + q];
            float4 c = ((const float4*)new_xyz_embed)[(size_t)center * (E / 4) + q];
            int ch = 4 * q;
            tile[(ch + 0) * TP + s] = v.x - c.x;
            tile[(ch + 1) * TP + s] = v.y - c.y;
            tile[(ch + 2) * TP + s] = v.z - c.z;
            tile[(ch + 3) * TP + s] = v.w - c.w;
        }
        // feat: 32 points x 16 float4 (two passes)
#pragma unroll
        for (int t = tid; t < S * (C / 4); t += 256) {
            int s = t >> 4;
            int q = t & 15;
            int p = sidx[c8][s];
            float4 v = ((const float4*)g_feat_t)[((size_t)b * N + p) * (C / 4) + q];
            int ch = E + 4 * q;
            tile[(ch + 0) * TP + s] = v.x;
            tile[(ch + 1) * TP + s] = v.y;
            tile[(ch + 2) * TP + s] = v.z;
            tile[(ch + 3) * TP + s] = v.w;
        }
        __syncthreads();

        float4* out4 = (float4*)out;
#pragma unroll
        for (int t = tid; t < NCH * (S / 4); t += 256) {
            int ch = t >> 3;
            int s4 = t & 7;
            const float* r = tile + ch * TP + 4 * s4;
            out4[(((size_t)b * NCH + ch) * M + m) * (S / 4) + s4] =
                make_float4(r[0], r[1], r[2], r[3]);
        }
        __syncthreads();                 // tile reused next iteration
    }
}

// ---------------- launch -----------------------------------------------------
extern "C" void kernel_launch(void* const* d_in, const int* in_sizes, int n_in,
                              void* d_out, int out_size) {
    const float* xyz           = (const float*)d_in[0];
    const float* xyz_embed     = (const float*)d_in[1];
    const float* new_xyz       = (const float*)d_in[2];
    const float* new_xyz_embed = (const float*)d_in[3];
    const float* features      = (const float*)d_in[4];
    float* out = (float*)d_out;

    prep_kernel<<<128 + 2048, 256>>>(xyz, features);
    grid_count_kernel<<<(B * N + 255) / 256, 256>>>();
    grid_scan_kernel<<<B, 1024>>>();
    grid_scatter_kernel<<<(B * N + 255) / 256, 256>>>();
    query_gather_kernel<<<B * M / 8, 256>>>(new_xyz, xyz_embed, new_xyz_embed, out);
}

// round 14
// speedup vs baseline: 2.3169x; 1.0923x over previous
#include <cuda_runtime.h>
#include <cuda_bf16.h>
#include <cstdint>

#define B 2
#define N 16384
#define M 4096
#define E 32
#define C 64
#define S 32
#define NCH 96
#define R2 0.01f
#define TP 37
#define GC 10
#define NCELL (GC * GC * GC)
#define CAP 128

// ---------------- scratch ----------------------------------------------------
__device__ float4 g_xyz4[B * N];                 // {x,y,z,norm} index order
__device__ __align__(16) float g_feat_t[(size_t)B * N * C];
__device__ int    g_cnt[B * NCELL];              // zero-init; re-zeroed by query_gather
__device__ int    g_fill[B * NCELL];             // zero-init; re-zeroed by query_gather
__device__ int    g_cellStart[B * (NCELL + 1)];
__device__ float4 g_ptmp[B * N];                 // cell-bucketed {x,y,z,idx}

// ---- frozen fp formulas (bit-exact vs XLA; do not touch) --------------------
__device__ __forceinline__ float norm3_nofma(float x, float y, float z) {
    return __fadd_rn(__fadd_rn(__fmul_rn(x, x), __fmul_rn(y, y)),
                     __fmul_rn(z, z));
}
__device__ __forceinline__ float dot3_fma(float ax, float ay, float az,
                                          float bx, float by, float bz) {
    return __fmaf_rn(az, bz, __fmaf_rn(ay, by, __fmul_rn(ax, bx)));
}
__device__ __forceinline__ int cell_of(float x, float y, float z) {
    int cx = min((int)(x * 10.0f), GC - 1);
    int cy = min((int)(y * 10.0f), GC - 1);
    int cz = min((int)(z * 10.0f), GC - 1);
    return (cz * GC + cy) * GC + cx;
}

// ------ K1: fused pack xyz + grid count | feature transpose ------------------
// blocks [0,128): pack + count (g_cnt pre-zeroed by previous launch / init).
// blocks [128, 128+2048): 32x32 transpose tiles.
__global__ __launch_bounds__(256) void prep_kernel(
        const float* __restrict__ xyz, const float* __restrict__ f) {
    if (blockIdx.x < 128) {
        int i = blockIdx.x * 256 + threadIdx.x;      // < B*N
        float x = xyz[3 * i + 0], y = xyz[3 * i + 1], z = xyz[3 * i + 2];
        g_xyz4[i] = make_float4(x, y, z, norm3_nofma(x, y, z));
        int b = i >> 14;
        atomicAdd(&g_cnt[b * NCELL + cell_of(x, y, z)], 1);
    } else {
        __shared__ float t[32][33];
        int bi = blockIdx.x - 128;
        int n0 = (bi & 511) * 32;
        int c0 = ((bi >> 9) & 1) * 32;
        int b  = bi >> 10;
        int tx = threadIdx.x & 31, ty = threadIdx.x >> 5;
#pragma unroll
        for (int i = 0; i < 32; i += 8)
            t[ty + i][tx] = f[((size_t)(b * C + c0 + ty + i)) * N + n0 + tx];
        __syncthreads();
#pragma unroll
        for (int i = 0; i < 32; i += 8)
            g_feat_t[((size_t)b * N + n0 + ty + i) * C + c0 + tx] = t[tx][ty + i];
    }
}

// ------ K2: fused in-block scan + scatter ------------------------------------
// 128 blocks x 256; each block redundantly scans its batch's 1000 counts in
// SMEM (deterministic), first block per batch publishes g_cellStart, then all
// blocks scatter their 256 points.
__global__ __launch_bounds__(256) void scan_scatter_kernel() {
    __shared__ int sstart[NCELL + 4];
    __shared__ int ws[8];
    int tid = threadIdx.x;
    int b = blockIdx.x >> 6;                 // 64 blocks per batch

    // load 4 cells/thread, thread-local sum
    int c0 = tid * 4;
    int v[4];
    int sum = 0;
#pragma unroll
    for (int k = 0; k < 4; k++) {
        int c = c0 + k;
        v[k] = (c < NCELL) ? g_cnt[b * NCELL + c] : 0;
        sum += v[k];
    }
    // warp inclusive scan of thread sums
    int lane = tid & 31, wid = tid >> 5;
    int x = sum;
#pragma unroll
    for (int o = 1; o < 32; o <<= 1) {
        int y = __shfl_up_sync(0xFFFFFFFFu, x, o);
        if (lane >= o) x += y;
    }
    if (lane == 31) ws[wid] = x;
    __syncthreads();
    if (wid == 0) {
        int z = (lane < 8) ? ws[lane] : 0;
#pragma unroll
        for (int o = 1; o < 8; o <<= 1) {
            int y = __shfl_up_sync(0xFFFFFFFFu, z, o);
            if (lane >= o) z += y;
        }
        if (lane < 8) ws[lane] = z;
    }
    __syncthreads();
    int excl = x - sum + (wid ? ws[wid - 1] : 0);
#pragma unroll
    for (int k = 0; k < 4; k++) {
        int c = c0 + k;
        if (c <= NCELL) sstart[c] = excl;
        excl += v[k];
    }
    __syncthreads();

    // first block of each batch publishes cellStart for the query kernel
    if ((blockIdx.x & 63) == 0)
        for (int t = tid; t <= NCELL; t += 256)
            g_cellStart[b * (NCELL + 1) + t] = sstart[t];

    // scatter this block's 256 points
    int i = blockIdx.x * 256 + tid;          // < B*N
    float4 q = g_xyz4[i];
    int c = cell_of(q.x, q.y, q.z);
    int pos = sstart[c] + atomicAdd(&g_fill[b * NCELL + c], 1);
    g_ptmp[b * N + pos] = make_float4(q.x, q.y, q.z, __int_as_float(i & (N - 1)));
}

// ---------------- fallback: ordered linear scan (proven correct) -------------
__device__ __noinline__ void linear_scan_center(
        float nx, float ny, float nz, float sn, int b, int* ob, int lane) {
    const float4* __restrict__ P = g_xyz4 + b * N;
    const unsigned FULL = 0xFFFFFFFFu;
    const unsigned lt = (1u << lane) - 1u;
    int cnt = 0, first = 0;
    for (int j0 = 0; j0 < N && cnt < S; j0 += 32) {
        float4 p = P[j0 + lane];
        int j = j0 + lane;
        float dot = dot3_fma(nx, ny, nz, p.x, p.y, p.z);
        float d2  = __fmaf_rn(-2.0f, dot, __fadd_rn(sn, p.w));
        bool hit  = d2 < R2;
        unsigned mask = __ballot_sync(FULL, hit);
        if (mask) {
            int pos = cnt + __popc(mask & lt);
            if (hit && pos < S) ob[pos] = j;
            if (cnt == 0) first = __shfl_sync(FULL, j, __ffs(mask) - 1);
            cnt += __popc(mask);
        }
    }
    if (lane >= cnt) ob[lane] = first;
}

// ---- generalized warp bitonic sort: NR*32 keys, NR regs/lane, ascending -----
template <int NR>
__device__ __forceinline__ void bitonic_sort_warp(int (&v)[NR], int lane) {
    const unsigned FULL = 0xFFFFFFFFu;
#pragma unroll
    for (int k = 2; k <= NR * 32; k <<= 1) {
#pragma unroll
        for (int j = NR * 16; j > 0; j >>= 1) {
            if (j >= k) continue;
            if (j >= 32) {               // cross-register (k >= 64 here)
                int jr = j >> 5;
#pragma unroll
                for (int r = 0; r < NR; r++) {
                    if ((r & jr) == 0) {
                        int r2 = r | jr;
                        bool up = (((r * 32) & k) == 0);
                        int a = v[r], c = v[r2];
                        int lo = min(a, c), hi = max(a, c);
                        v[r]  = up ? lo : hi;
                        v[r2] = up ? hi : lo;
                    }
                }
            } else {
#pragma unroll
                for (int r = 0; r < NR; r++) {
                    int other = __shfl_xor_sync(FULL, v[r], j);
                    bool up = (((r * 32 + lane) & k) == 0);
                    bool lower = ((lane & j) == 0);
                    v[r] = (up == lower) ? min(v[r], other) : max(v[r], other);
                }
            }
        }
    }
}

template <int NR>
__device__ __forceinline__ void sort_emit(const int* bufw, int cnt, int lane,
                                          int* ob) {
    int v[NR];
#pragma unroll
    for (int r = 0; r < NR; r++) {
        int t = r * 32 + lane;
        v[r] = (t < cnt) ? bufw[t] : 0x7FFFFFFF;
    }
    bitonic_sort_warp<NR>(v, lane);
    int my = v[0];
    int first = __shfl_sync(0xFFFFFFFFu, my, 0);
    if (cnt == 0) first = 0;
    ob[lane] = (lane < cnt) ? my : first;
}

// ------ K3: fused ball query (warp/center) + gather (block/8 centers) --------
// Also re-zeroes g_cnt/g_fill for the next graph replay (blocks 0..7).
__global__ __launch_bounds__(256) void query_gather_kernel(
        const float* __restrict__ new_xyz,
        const float* __restrict__ xyz_embed,
        const float* __restrict__ new_xyz_embed,
        float* __restrict__ out) {
    __shared__ int   buf[8][CAP];
    __shared__ int   sidx[8][S];
    __shared__ float tile[NCH * TP];

    int w    = threadIdx.x >> 5;
    int lane = threadIdx.x & 31;
    int tid  = threadIdx.x;
    int gw   = blockIdx.x * 8 + w;        // this warp's center
    const unsigned FULL = 0xFFFFFFFFu;
    const unsigned lt   = (1u << lane) - 1u;

    // re-zero grid counters for the next launch (nothing reads them here)
    if (blockIdx.x < 8) {
        int z = blockIdx.x * 256 + tid;
        if (z < B * NCELL) { g_cnt[z] = 0; g_fill[z] = 0; }
    }

    // ================= query phase (warp per center) =================
    {
        int b = gw >> 12;
        const float nx = new_xyz[3 * gw + 0];
        const float ny = new_xyz[3 * gw + 1];
        const float nz = new_xyz[3 * gw + 2];
        const float sn = norm3_nofma(nx, ny, nz);

        const float4* __restrict__ P = g_ptmp + b * N;
        const int* __restrict__ cs = g_cellStart + b * (NCELL + 1);

        int z0 = max(0, (int)floorf((nz - 0.1001f) * 10.f));
        int z1 = min(GC - 1, (int)floorf((nz + 0.1001f) * 10.f));
        int y0 = max(0, (int)floorf((ny - 0.1001f) * 10.f));
        int y1 = min(GC - 1, (int)floorf((ny + 0.1001f) * 10.f));

        int cnt = 0;
        for (int gz = z0; gz <= z1; gz++) {
            float dz = fmaxf(fmaxf(0.1f * gz - nz, nz - 0.1f * (gz + 1)), 0.f);
            for (int gy = y0; gy <= y1; gy++) {
                float dy = fmaxf(fmaxf(0.1f * gy - ny, ny - 0.1f * (gy + 1)), 0.f);
                float rem = (R2 + 2e-4f) - __fmaf_rn(dy, dy, dz * dz);
                if (rem <= 0.f) continue;
                // conservative per-row x-trim: |px-nx| <= sqrt(rem)
                float hwf = sqrtf(rem) + 1e-4f;
                int xa = max(0, (int)floorf((nx - hwf) * 10.f));
                int xb = min(GC - 1, (int)floorf((nx + hwf) * 10.f));
                if (xa > xb) continue;
                int base = (gz * GC + gy) * GC;
                int sS = cs[base + xa];
                int sE = cs[base + xb + 1];
                for (int p0 = sS; p0 < sE; p0 += 32) {
                    int pi = p0 + lane;
                    bool valid = pi < sE;
                    float4 pt = valid ? P[pi] : make_float4(9.f, 9.f, 9.f, 0.f);
                    float sp  = norm3_nofma(pt.x, pt.y, pt.z);
                    float dot = dot3_fma(nx, ny, nz, pt.x, pt.y, pt.z);
                    float d2  = __fmaf_rn(-2.0f, dot, __fadd_rn(sn, sp));
                    bool hit  = valid && (d2 < R2);
                    unsigned mask = __ballot_sync(FULL, hit);
                    if (mask) {
                        int pos = cnt + __popc(mask & lt);
                        if (hit && pos < CAP) buf[w][pos] = __float_as_int(pt.w);
                        cnt += __popc(mask);
                    }
                }
            }
        }
        __syncwarp();

        if (cnt > CAP) {                 // astronomically rare: proven fallback
            linear_scan_center(nx, ny, nz, sn, b, sidx[w], lane);
        } else if (cnt <= 32) {
            sort_emit<1>(buf[w], cnt, lane, sidx[w]);
        } else if (cnt <= 64) {
            sort_emit<2>(buf[w], cnt, lane, sidx[w]);
        } else {
            sort_emit<4>(buf[w], cnt, lane, sidx[w]);
        }
    }
    __syncthreads();

    // ================= gather phase (block per center, 8 iterations) =========
#pragma unroll 1
    for (int c8 = 0; c8 < 8; c8++) {
        int center = blockIdx.x * 8 + c8;
        int b = center >> 12;
        int m = center & (M - 1);

        // embed: 32 points x 8 float4 (one pass)
        {
            int s = tid >> 3;
            int q = tid & 7;
            int p = sidx[c8][s];
            float4 v = ((const float4*)xyz_embed)[((size_t)b * N + p) * (E / 4) + q];
            float4 c = ((const float4*)new_xyz_embed)[(size_t)center * (E / 4) + q];
            int ch = 4 * q;
            tile[(ch + 0) * TP + s] = v.x - c.x;
            tile[(ch + 1) * TP + s] = v.y - c.y;
            tile[(ch + 2) * TP + s] = v.z - c.z;
            tile[(ch + 3) * TP + s] = v.w - c.w;
        }
        // feat: 32 points x 16 float4 (two passes)
#pragma unroll
        for (int t = tid; t < S * (C / 4); t += 256) {
            int s = t >> 4;
            int q = t & 15;
            int p = sidx[c8][s];
            float4 v = ((const float4*)g_feat_t)[((size_t)b * N + p) * (C / 4) + q];
            int ch = E + 4 * q;
            tile[(ch + 0) * TP + s] = v.x;
            tile[(ch + 1) * TP + s] = v.y;
            tile[(ch + 2) * TP + s] = v.z;
            tile[(ch + 3) * TP + s] = v.w;
        }
        __syncthreads();

        float4* out4 = (float4*)out;
#pragma unroll
        for (int t = tid; t < NCH * (S / 4); t += 256) {
            int ch = t >> 3;
            int s4 = t & 7;
            const float* r = tile + ch * TP + 4 * s4;
            out4[(((size_t)b * NCH + ch) * M + m) * (S / 4) + s4] =
                make_float4(r[0], r[1], r[2], r[3]);
        }
        __syncthreads();                 // tile reused next iteration
    }
}

// ---------------- launch -----------------------------------------------------
extern "C" void kernel_launch(void* const* d_in, const int* in_sizes, int n_in,
                              void* d_out, int out_size) {
    const float* xyz           = (const float*)d_in[0];
    const float* xyz_embed     = (const float*)d_in[1];
    const float* new_xyz       = (const float*)d_in[2];
    const float* new_xyz_embed = (const float*)d_in[3];
    const float* features      = (const float*)d_in[4];
    float* out = (float*)d_out;

    prep_kernel<<<128 + 2048, 256>>>(xyz, features);
    scan_scatter_kernel<<<128, 256>>>();
    query_gather_kernel<<<B * M / 8, 256>>>(new_xyz, xyz_embed, new_xyz_embed, out);
}